// round 1
// baseline (speedup 1.0000x reference)
#include <cuda_runtime.h>
#include <cstdint>
#include <cstddef>

// Problem dims (fixed by the dataset).
#define TDIM 8192
#define EDIM 4096

// Scratch: q, k, v [T,E]; S (logits/att) [E,E]; attT [E,E].
// outT [T,E] reuses g_q (q is dead after the logits GEMM).
__device__ float g_q[(size_t)TDIM * EDIM];
__device__ float g_k[(size_t)TDIM * EDIM];
__device__ float g_v[(size_t)TDIM * EDIM];
__device__ float g_s[(size_t)EDIM * EDIM];
__device__ float g_st[(size_t)EDIM * EDIM];

#define BM 128
#define BN 128
#define BK 16

// ---- packed f32x2 helpers (sm_103a) ----
__device__ __forceinline__ unsigned long long pack2(float x) {
    unsigned long long r;
    asm("mov.b64 %0, {%1, %1};" : "=l"(r) : "f"(x));
    return r;
}
__device__ __forceinline__ void fma2(unsigned long long& acc,
                                     unsigned long long a, unsigned long long b) {
    asm("fma.rn.f32x2 %0, %1, %2, %0;" : "+l"(acc) : "l"(a), "l"(b));
}
__device__ __forceinline__ void unpack2(unsigned long long p, float& lo, float& hi) {
    asm("mov.b64 {%0, %1}, %2;" : "=f"(lo), "=f"(hi) : "l"(p));
}

// Generic tiled GEMM: C[M,N] = A ? B + bias (bias over N, may be null).
// AKMAJOR=true : A is [M,K] row-major (K contiguous)  -> transpose-on-store into smem.
// AKMAJOR=false: A is [K,M] row-major (M contiguous)  -> direct copy ("A^T @ B" form).
// B is always [K,N] row-major. All of M,N multiples of 128; K multiple of 16.
template <bool AKMAJOR>
__global__ __launch_bounds__(256, 2)
void gemm_kernel(const float* __restrict__ A, const float* __restrict__ B,
                 float* __restrict__ C, const float* __restrict__ bias,
                 int M, int N, int K)
{
    __shared__ float As[BK][BM + 4];
    __shared__ float Bs[BK][BN];

    const int tid = threadIdx.x;          // 256 threads
    const int tx = tid & 15;              // 16 x 16 thread grid
    const int ty = tid >> 4;
    const int bm = blockIdx.y * BM;
    const int bn = blockIdx.x * BN;

    unsigned long long acc[8][4];
    #pragma unroll
    for (int i = 0; i < 8; i++)
        #pragma unroll
        for (int j = 0; j < 4; j++) acc[i][j] = 0ull;

    for (int k0 = 0; k0 < K; k0 += BK) {
        // ---- load A tile into As[k][m] ----
        if (AKMAJOR) {
            #pragma unroll
            for (int i = 0; i < 2; i++) {
                int idx = tid + i * 256;          // 0..511 float4 loads
                int m  = idx >> 2;                // 0..127
                int kq = (idx & 3) << 2;          // 0,4,8,12
                float4 va = *reinterpret_cast<const float4*>(
                    A + (size_t)(bm + m) * K + k0 + kq);
                As[kq + 0][m] = va.x;
                As[kq + 1][m] = va.y;
                As[kq + 2][m] = va.z;
                As[kq + 3][m] = va.w;
            }
        } else {
            #pragma unroll
            for (int i = 0; i < 2; i++) {
                int idx = tid + i * 256;
                int kk = idx >> 5;                // 0..15
                int mq = (idx & 31) << 2;         // 0..124
                *reinterpret_cast<float4*>(&As[kk][mq]) =
                    *reinterpret_cast<const float4*>(
                        A + (size_t)(k0 + kk) * M + bm + mq);
            }
        }
        // ---- load B tile (always direct) ----
        #pragma unroll
        for (int i = 0; i < 2; i++) {
            int idx = tid + i * 256;
            int kk = idx >> 5;
            int nq = (idx & 31) << 2;
            *reinterpret_cast<float4*>(&Bs[kk][nq]) =
                *reinterpret_cast<const float4*>(
                    B + (size_t)(k0 + kk) * N + bn + nq);
        }
        __syncthreads();

        // ---- 8x8 per-thread microkernel via packed f32x2 FMA ----
        #pragma unroll
        for (int kk = 0; kk < BK; kk++) {
            float4 a0 = *reinterpret_cast<const float4*>(&As[kk][ty * 4]);
            float4 a1 = *reinterpret_cast<const float4*>(&As[kk][ty * 4 + 64]);
            ulonglong2 b0 = *reinterpret_cast<const ulonglong2*>(&Bs[kk][tx * 4]);
            ulonglong2 b1 = *reinterpret_cast<const ulonglong2*>(&Bs[kk][tx * 4 + 64]);
            unsigned long long A2[8];
            A2[0] = pack2(a0.x); A2[1] = pack2(a0.y);
            A2[2] = pack2(a0.z); A2[3] = pack2(a0.w);
            A2[4] = pack2(a1.x); A2[5] = pack2(a1.y);
            A2[6] = pack2(a1.z); A2[7] = pack2(a1.w);
            #pragma unroll
            for (int m = 0; m < 8; m++) {
                fma2(acc[m][0], A2[m], b0.x);
                fma2(acc[m][1], A2[m], b0.y);
                fma2(acc[m][2], A2[m], b1.x);
                fma2(acc[m][3], A2[m], b1.y);
            }
        }
        __syncthreads();
    }

    // ---- epilogue: unpack, add bias, store ----
    const int c0 = bn + tx * 4;
    const int c1 = bn + 64 + tx * 4;
    #pragma unroll
    for (int m = 0; m < 8; m++) {
        int r = bm + ((m & 4) << 4) + ty * 4 + (m & 3);
        float o[8];
        unpack2(acc[m][0], o[0], o[1]);
        unpack2(acc[m][1], o[2], o[3]);
        unpack2(acc[m][2], o[4], o[5]);
        unpack2(acc[m][3], o[6], o[7]);
        if (bias != nullptr) {
            o[0] += bias[c0 + 0]; o[1] += bias[c0 + 1];
            o[2] += bias[c0 + 2]; o[3] += bias[c0 + 3];
            o[4] += bias[c1 + 0]; o[5] += bias[c1 + 1];
            o[6] += bias[c1 + 2]; o[7] += bias[c1 + 3];
        }
        *reinterpret_cast<float4*>(C + (size_t)r * N + c0) =
            make_float4(o[0], o[1], o[2], o[3]);
        *reinterpret_cast<float4*>(C + (size_t)r * N + c1) =
            make_float4(o[4], o[5], o[6], o[7]);
    }
}

// Row softmax over S [rows x n], n = 4096, 256 threads, 16 elems/thread.
__global__ void softmax_rows(float* __restrict__ S, int n)
{
    const int tid = threadIdx.x;
    float* p = S + (size_t)blockIdx.x * n;
    float v[16];
    float m = -3.4e38f;
    #pragma unroll
    for (int i = 0; i < 16; i++) {
        v[i] = p[tid + (i << 8)];
        m = fmaxf(m, v[i]);
    }
    __shared__ float red[8];
    #pragma unroll
    for (int o = 16; o > 0; o >>= 1)
        m = fmaxf(m, __shfl_xor_sync(0xffffffffu, m, o));
    if ((tid & 31) == 0) red[tid >> 5] = m;
    __syncthreads();
    float M = red[0];
    #pragma unroll
    for (int i = 1; i < 8; i++) M = fmaxf(M, red[i]);

    float s = 0.f;
    #pragma unroll
    for (int i = 0; i < 16; i++) {
        v[i] = expf(v[i] - M);
        s += v[i];
    }
    __syncthreads();  // red[] reuse
    #pragma unroll
    for (int o = 16; o > 0; o >>= 1)
        s += __shfl_xor_sync(0xffffffffu, s, o);
    if ((tid & 31) == 0) red[tid >> 5] = s;
    __syncthreads();
    float tot = 0.f;
    #pragma unroll
    for (int i = 0; i < 8; i++) tot += red[i];
    const float inv = 1.0f / tot;
    #pragma unroll
    for (int i = 0; i < 16; i++) p[tid + (i << 8)] = v[i] * inv;
}

// Square transpose (n x n), n multiple of 32. Block (32,8).
__global__ void transpose_kernel(const float* __restrict__ in,
                                 float* __restrict__ out, int n)
{
    __shared__ float tile[32][33];
    int x = blockIdx.x * 32 + threadIdx.x;
    int y = blockIdx.y * 32 + threadIdx.y;
    #pragma unroll
    for (int j = 0; j < 32; j += 8)
        tile[threadIdx.y + j][threadIdx.x] = in[(size_t)(y + j) * n + x];
    __syncthreads();
    x = blockIdx.y * 32 + threadIdx.x;
    y = blockIdx.x * 32 + threadIdx.y;
    #pragma unroll
    for (int j = 0; j < 32; j += 8)
        out[(size_t)(y + j) * n + x] = tile[threadIdx.x][threadIdx.y + j];
}

extern "C" void kernel_launch(void* const* d_in, const int* in_sizes, int n_in,
                              void* d_out, int out_size)
{
    (void)in_sizes; (void)n_in; (void)out_size;
    const float* tokens = (const float*)d_in[0];
    const float* Wq = (const float*)d_in[1];
    const float* bq = (const float*)d_in[2];
    const float* Wk = (const float*)d_in[3];
    const float* bk = (const float*)d_in[4];
    const float* Wv = (const float*)d_in[5];
    const float* bv = (const float*)d_in[6];
    const float* Wp = (const float*)d_in[7];
    const float* bp = (const float*)d_in[8];
    float* out = (float*)d_out;

    float *q, *k, *v, *s, *st;
    cudaGetSymbolAddress((void**)&q,  g_q);
    cudaGetSymbolAddress((void**)&k,  g_k);
    cudaGetSymbolAddress((void**)&v,  g_v);
    cudaGetSymbolAddress((void**)&s,  g_s);
    cudaGetSymbolAddress((void**)&st, g_st);

    const int T = TDIM, E = EDIM;

    // QKV projections: [T,E] = tokens[T,E] @ W[E,E] + b   (NN form)
    dim3 gQKV(E / BN, T / BM);
    gemm_kernel<true><<<gQKV, 256>>>(tokens, Wq, q, bq, T, E, E);
    gemm_kernel<true><<<gQKV, 256>>>(tokens, Wk, k, bk, T, E, E);
    gemm_kernel<true><<<gQKV, 256>>>(tokens, Wv, v, bv, T, E, E);

    // Logits S[E,E] = q^T @ k   (TN form: both operands K(=T)-major)
    dim3 gS(E / BN, E / BM);
    gemm_kernel<false><<<gS, 256>>>(q, k, s, nullptr, E, E, T);

    // Row softmax (in place).
    softmax_rows<<<E, 256>>>(s, E);

    // attT[e,i] = att[i,e]
    transpose_kernel<<<dim3(E / 32, E / 32), dim3(32, 8)>>>(s, st, E);

    // outT[t,i] = sum_e v[t,e] * attT[e,i]   (NN form; reuse g_q as outT)
    gemm_kernel<true><<<dim3(E / BN, T / BM), 256>>>(v, st, q, nullptr, T, E, E);

    // result[i,j] = sum_t outT[t,i] * Wp[t,j] + bp[j]   (TN form)
    gemm_kernel<false><<<dim3(T / BN, E / BM), 256>>>(q, Wp, out, bp, E, T, T);
}

// round 3
// speedup vs baseline: 2.0874x; 2.0874x over previous
#include <cuda_runtime.h>
#include <cuda_bf16.h>
#include <cstdint>
#include <cstddef>

#define TT 8192
#define EE 4096

// ---------------- scratch (device globals; no allocations allowed) ----------
__device__ __nv_bfloat16 g_tokH[(size_t)TT * EE];   // tokens hi; reused as outH [E,T]
__device__ __nv_bfloat16 g_tokL[(size_t)TT * EE];   // tokens lo; reused as outL [E,T]
__device__ __nv_bfloat16 g_wtH[(size_t)EE * EE];    // W^T hi (reused for Wq/Wk/Wv)
__device__ __nv_bfloat16 g_wtL[(size_t)EE * EE];
__device__ __nv_bfloat16 g_wpH[(size_t)TT * TT];    // Wp^T hi
__device__ __nv_bfloat16 g_wpL[(size_t)TT * TT];
__device__ float g_f1[(size_t)TT * EE];             // q fp32; later out [E,T]
__device__ float g_f2[(size_t)TT * EE];             // k fp32
__device__ float g_f3[(size_t)TT * EE];             // v fp32
__device__ __nv_bfloat16 g_qtH[(size_t)EE * TT];    // q^T hi  [E,T]
__device__ __nv_bfloat16 g_qtL[(size_t)EE * TT];
__device__ __nv_bfloat16 g_ktH[(size_t)EE * TT];
__device__ __nv_bfloat16 g_ktL[(size_t)EE * TT];
__device__ __nv_bfloat16 g_vH[(size_t)TT * EE];
__device__ __nv_bfloat16 g_vL[(size_t)TT * EE];
__device__ float g_S[(size_t)EE * EE];              // logits / att fp32
__device__ __nv_bfloat16 g_attH[(size_t)EE * EE];
__device__ __nv_bfloat16 g_attL[(size_t)EE * EE];

// ---------------- helpers ---------------------------------------------------
__device__ __forceinline__ uint32_t s2u(const void* p) {
    uint32_t a;
    asm("{ .reg .u64 t; cvta.to.shared.u64 t, %1; cvt.u32.u64 %0, t; }"
        : "=r"(a) : "l"(p));
    return a;
}
__device__ __forceinline__ void cp16(uint32_t dst, const void* src) {
    asm volatile("cp.async.cg.shared.global [%0], [%1], 16;"
                 :: "r"(dst), "l"(src));
}
#define CP_COMMIT() asm volatile("cp.async.commit_group;" ::: "memory")
#define CP_WAIT2()  asm volatile("cp.async.wait_group 2;" ::: "memory")

#define LDSM4(r, a)                                                          \
    asm volatile("ldmatrix.sync.aligned.m8n8.x4.shared.b16 "                 \
                 "{%0,%1,%2,%3}, [%4];"                                      \
                 : "=r"((r)[0]), "=r"((r)[1]), "=r"((r)[2]), "=r"((r)[3])    \
                 : "r"(a))

#define MMA16816(c, a, b0, b1)                                               \
    asm volatile("mma.sync.aligned.m16n8k16.row.col.f32.bf16.bf16.f32 "      \
                 "{%0,%1,%2,%3}, {%4,%5,%6,%7}, {%8,%9}, {%0,%1,%2,%3};"     \
                 : "+f"((c)[0]), "+f"((c)[1]), "+f"((c)[2]), "+f"((c)[3])    \
                 : "r"((a)[0]), "r"((a)[1]), "r"((a)[2]), "r"((a)[3]),       \
                   "r"(b0), "r"(b1))

// ---------------- split-bf16 HMMA GEMM --------------------------------------
// C[M,N] = sum_k A[m,k]*B[n,k] (+bias[n]); A,B bf16 hi/lo pairs, K-major.
// M % 128 == 0, N % 256 == 0, K % 32 == 0.
#define BM 128
#define BN 256
#define BKT 32
#define PITCH 80            // 64B row + 16B pad -> conflict-free ldmatrix
#define A_HL 10240          // 128 * 80
#define B_OFF 20480         // A takes 2 * 10240
#define B_HL 20480          // 256 * 80
#define STAGE 61440
#define NST 3

__global__ __launch_bounds__(256, 1)
void gemm_mma(const __nv_bfloat16* __restrict__ Ah, const __nv_bfloat16* __restrict__ Al,
              const __nv_bfloat16* __restrict__ Bh, const __nv_bfloat16* __restrict__ Bl,
              float* __restrict__ C, const float* __restrict__ bias,
              int M, int N, int K)
{
    extern __shared__ char dsm[];
    const uint32_t sb = s2u(dsm);

    const int tid  = threadIdx.x;
    const int wid  = tid >> 5;
    const int lane = tid & 31;
    const int bm = blockIdx.y * BM;
    const int bn = blockIdx.x * BN;
    const int m0 = (wid >> 2) * 64;
    const int n0 = (wid & 3) * 64;
    const int kt = K / BKT;

    // producer: fill stage slot with K-tile `tile` (3072 x 16B chunks, 12/thread)
    auto load_stage = [&](int slot, int tile) {
        const uint32_t base = sb + slot * STAGE;
        const int k0 = tile * BKT;
        #pragma unroll
        for (int j = 0; j < 12; j++) {
            int c = tid + j * 256;
            uint32_t dst;
            const __nv_bfloat16* src;
            if (c < 1024) {                       // A: 2 x 128 rows x 4 chunks
                int hl = c >> 9, row = (c >> 2) & 127, ch = c & 3;
                dst = base + hl * A_HL + row * PITCH + ch * 16;
                const __nv_bfloat16* p = hl ? Al : Ah;
                src = p + (size_t)(bm + row) * K + k0 + ch * 8;
            } else {                              // B: 2 x 256 rows x 4 chunks
                int cc = c - 1024;
                int hl = cc >> 10, row = (cc >> 2) & 255, ch = cc & 3;
                dst = base + B_OFF + hl * B_HL + row * PITCH + ch * 16;
                const __nv_bfloat16* p = hl ? Bl : Bh;
                src = p + (size_t)(bn + row) * K + k0 + ch * 8;
            }
            cp16(dst, src);
        }
    };

    float acc[4][8][4];
    #pragma unroll
    for (int mt = 0; mt < 4; mt++)
        #pragma unroll
        for (int nt = 0; nt < 8; nt++)
            #pragma unroll
            for (int r = 0; r < 4; r++) acc[mt][nt][r] = 0.f;

    // per-lane ldmatrix base offsets
    const uint32_t rowA = (uint32_t)(m0 + (lane & 15)) * PITCH + ((lane >> 4) << 4);
    const int quad = lane >> 3, rl = lane & 7;
    const uint32_t rowB = (uint32_t)(n0 + ((quad >> 1) << 3) + rl) * PITCH
                        + ((quad & 1) << 4);

    // prefetch 3 stages
    load_stage(0, 0); CP_COMMIT();
    load_stage(1, 1); CP_COMMIT();
    load_stage(2, 2); CP_COMMIT();

    for (int i = 0; i < kt; i++) {
        CP_WAIT2();
        __syncthreads();
        const uint32_t base = sb + (i % NST) * STAGE;

        #pragma unroll
        for (int ks = 0; ks < 2; ks++) {
            uint32_t ah[4][4], al[4][4], b[4][4];
            const uint32_t ko = ks * 32;
            // Ah, Bh
            #pragma unroll
            for (int mt = 0; mt < 4; mt++)
                LDSM4(ah[mt], base + rowA + mt * (16 * PITCH) + ko);
            #pragma unroll
            for (int np = 0; np < 4; np++)
                LDSM4(b[np], base + B_OFF + rowB + np * (16 * PITCH) + ko);
            // hh
            #pragma unroll
            for (int mt = 0; mt < 4; mt++)
                #pragma unroll
                for (int nt = 0; nt < 8; nt++)
                    MMA16816(acc[mt][nt], ah[mt], b[nt >> 1][(nt & 1) * 2],
                             b[nt >> 1][(nt & 1) * 2 + 1]);
            // Al, lh
            #pragma unroll
            for (int mt = 0; mt < 4; mt++)
                LDSM4(al[mt], base + A_HL + rowA + mt * (16 * PITCH) + ko);
            #pragma unroll
            for (int mt = 0; mt < 4; mt++)
                #pragma unroll
                for (int nt = 0; nt < 8; nt++)
                    MMA16816(acc[mt][nt], al[mt], b[nt >> 1][(nt & 1) * 2],
                             b[nt >> 1][(nt & 1) * 2 + 1]);
            // Bl, hl
            #pragma unroll
            for (int np = 0; np < 4; np++)
                LDSM4(b[np], base + B_OFF + B_HL + rowB + np * (16 * PITCH) + ko);
            #pragma unroll
            for (int mt = 0; mt < 4; mt++)
                #pragma unroll
                for (int nt = 0; nt < 8; nt++)
                    MMA16816(acc[mt][nt], ah[mt], b[nt >> 1][(nt & 1) * 2],
                             b[nt >> 1][(nt & 1) * 2 + 1]);
        }

        __syncthreads();
        if (i + NST < kt) load_stage(i % NST, i + NST);
        CP_COMMIT();
    }

    // epilogue: regs -> C (+bias)
    const int r1 = lane >> 2;
    const int cb = (lane & 3) * 2;
    #pragma unroll
    for (int nt = 0; nt < 8; nt++) {
        const int col = bn + n0 + nt * 8 + cb;
        float b0 = 0.f, b1 = 0.f;
        if (bias != nullptr) { b0 = bias[col]; b1 = bias[col + 1]; }
        #pragma unroll
        for (int mt = 0; mt < 4; mt++) {
            const int row = bm + m0 + mt * 16 + r1;
            float2 v0 = make_float2(acc[mt][nt][0] + b0, acc[mt][nt][1] + b1);
            float2 v1 = make_float2(acc[mt][nt][2] + b0, acc[mt][nt][3] + b1);
            *reinterpret_cast<float2*>(C + (size_t)row * N + col) = v0;
            *reinterpret_cast<float2*>(C + (size_t)(row + 8) * N + col) = v1;
        }
    }
}

// ---------------- split / transpose preps ----------------------------------
__global__ void split_kernel(const float* __restrict__ in,
                             __nv_bfloat16* __restrict__ oh,
                             __nv_bfloat16* __restrict__ ol, size_t n4)
{
    size_t i = (size_t)blockIdx.x * 256 + threadIdx.x;
    if (i >= n4) return;
    float4 v = reinterpret_cast<const float4*>(in)[i];
    __nv_bfloat16 h0 = __float2bfloat16(v.x), h1 = __float2bfloat16(v.y);
    __nv_bfloat16 h2 = __float2bfloat16(v.z), h3 = __float2bfloat16(v.w);
    __nv_bfloat16 l0 = __float2bfloat16(v.x - __bfloat162float(h0));
    __nv_bfloat16 l1 = __float2bfloat16(v.y - __bfloat162float(h1));
    __nv_bfloat16 l2 = __float2bfloat16(v.z - __bfloat162float(h2));
    __nv_bfloat16 l3 = __float2bfloat16(v.w - __bfloat162float(h3));
    __nv_bfloat162 H0; H0.x = h0; H0.y = h1;
    __nv_bfloat162 H1; H1.x = h2; H1.y = h3;
    __nv_bfloat162 L0; L0.x = l0; L0.y = l1;
    __nv_bfloat162 L1; L1.x = l2; L1.y = l3;
    reinterpret_cast<__nv_bfloat162*>(oh)[2 * i]     = H0;
    reinterpret_cast<__nv_bfloat162*>(oh)[2 * i + 1] = H1;
    reinterpret_cast<__nv_bfloat162*>(ol)[2 * i]     = L0;
    reinterpret_cast<__nv_bfloat162*>(ol)[2 * i + 1] = L1;
}

// in [R,C] fp32 -> oh/ol [C,R] bf16 (out[c][r] = in[r][c])
__global__ void splitT_kernel(const float* __restrict__ in,
                              __nv_bfloat16* __restrict__ oh,
                              __nv_bfloat16* __restrict__ ol, int R, int C)
{
    __shared__ float t[32][33];
    int x  = blockIdx.x * 32 + threadIdx.x;
    int y0 = blockIdx.y * 32;
    #pragma unroll
    for (int j = 0; j < 32; j += 8)
        t[threadIdx.y + j][threadIdx.x] = in[(size_t)(y0 + threadIdx.y + j) * C + x];
    __syncthreads();
    int ox  = y0 + threadIdx.x;
    int oy0 = blockIdx.x * 32;
    #pragma unroll
    for (int j = 0; j < 32; j += 8) {
        float v = t[threadIdx.x][threadIdx.y + j];
        __nv_bfloat16 h = __float2bfloat16(v);
        __nv_bfloat16 l = __float2bfloat16(v - __bfloat162float(h));
        size_t idx = (size_t)(oy0 + threadIdx.y + j) * R + ox;
        oh[idx] = h;
        ol[idx] = l;
    }
}

// ---------------- softmax ---------------------------------------------------
__global__ void softmax_rows(float* __restrict__ S, int n)
{
    const int tid = threadIdx.x;
    float* p = S + (size_t)blockIdx.x * n;
    float v[16];
    float m = -3.4e38f;
    #pragma unroll
    for (int i = 0; i < 16; i++) {
        v[i] = p[tid + (i << 8)];
        m = fmaxf(m, v[i]);
    }
    __shared__ float red[8];
    #pragma unroll
    for (int o = 16; o > 0; o >>= 1)
        m = fmaxf(m, __shfl_xor_sync(0xffffffffu, m, o));
    if ((tid & 31) == 0) red[tid >> 5] = m;
    __syncthreads();
    float M = red[0];
    #pragma unroll
    for (int i = 1; i < 8; i++) M = fmaxf(M, red[i]);

    float s = 0.f;
    #pragma unroll
    for (int i = 0; i < 16; i++) {
        v[i] = expf(v[i] - M);
        s += v[i];
    }
    __syncthreads();
    #pragma unroll
    for (int o = 16; o > 0; o >>= 1)
        s += __shfl_xor_sync(0xffffffffu, s, o);
    if ((tid & 31) == 0) red[tid >> 5] = s;
    __syncthreads();
    float tot = 0.f;
    #pragma unroll
    for (int i = 0; i < 8; i++) tot += red[i];
    const float inv = 1.0f / tot;
    #pragma unroll
    for (int i = 0; i < 16; i++) p[tid + (i << 8)] = v[i] * inv;
}

// ---------------- host ------------------------------------------------------
extern "C" void kernel_launch(void* const* d_in, const int* in_sizes, int n_in,
                              void* d_out, int out_size)
{
    (void)in_sizes; (void)n_in; (void)out_size;
    const float* tokens = (const float*)d_in[0];
    const float* Wq = (const float*)d_in[1];
    const float* bq = (const float*)d_in[2];
    const float* Wk = (const float*)d_in[3];
    const float* bk = (const float*)d_in[4];
    const float* Wv = (const float*)d_in[5];
    const float* bv = (const float*)d_in[6];
    const float* Wp = (const float*)d_in[7];
    const float* bp = (const float*)d_in[8];
    float* out = (float*)d_out;

    __nv_bfloat16 *tokH, *tokL, *wtH, *wtL, *wpH, *wpL;
    __nv_bfloat16 *qtH, *qtL, *ktH, *ktL, *vH, *vL, *attH, *attL;
    float *f1, *f2, *f3, *S;
    cudaGetSymbolAddress((void**)&tokH, g_tokH);
    cudaGetSymbolAddress((void**)&tokL, g_tokL);
    cudaGetSymbolAddress((void**)&wtH, g_wtH);
    cudaGetSymbolAddress((void**)&wtL, g_wtL);
    cudaGetSymbolAddress((void**)&wpH, g_wpH);
    cudaGetSymbolAddress((void**)&wpL, g_wpL);
    cudaGetSymbolAddress((void**)&qtH, g_qtH);
    cudaGetSymbolAddress((void**)&qtL, g_qtL);
    cudaGetSymbolAddress((void**)&ktH, g_ktH);
    cudaGetSymbolAddress((void**)&ktL, g_ktL);
    cudaGetSymbolAddress((void**)&vH, g_vH);
    cudaGetSymbolAddress((void**)&vL, g_vL);
    cudaGetSymbolAddress((void**)&attH, g_attH);
    cudaGetSymbolAddress((void**)&attL, g_attL);
    cudaGetSymbolAddress((void**)&f1, g_f1);
    cudaGetSymbolAddress((void**)&f2, g_f2);
    cudaGetSymbolAddress((void**)&f3, g_f3);
    cudaGetSymbolAddress((void**)&S, g_S);

    const int T = TT, E = EE;
    const size_t TE4 = (size_t)T * E / 4;
    const size_t EE4 = (size_t)E * E / 4;

    static bool attr_set = false;
    if (!attr_set) {
        cudaFuncSetAttribute(gemm_mma, cudaFuncAttributeMaxDynamicSharedMemorySize,
                             NST * STAGE);
        attr_set = true;
    }
    const size_t smem = NST * STAGE;
    dim3 blkT(32, 8);

    // prep: split tokens, transpose+split Wp
    split_kernel<<<(unsigned)(TE4 / 256), 256>>>(tokens, tokH, tokL, TE4);
    splitT_kernel<<<dim3(T / 32, T / 32), blkT>>>(Wp, wpH, wpL, T, T);

    // QKV projections: [T,E] = tokens @ W + b
    splitT_kernel<<<dim3(E / 32, E / 32), blkT>>>(Wq, wtH, wtL, E, E);
    gemm_mma<<<dim3(E / BN, T / BM), 256, smem>>>(tokH, tokL, wtH, wtL, f1, bq, T, E, E);
    splitT_kernel<<<dim3(E / 32, E / 32), blkT>>>(Wk, wtH, wtL, E, E);
    gemm_mma<<<dim3(E / BN, T / BM), 256, smem>>>(tokH, tokL, wtH, wtL, f2, bk, T, E, E);
    splitT_kernel<<<dim3(E / 32, E / 32), blkT>>>(Wv, wtH, wtL, E, E);
    gemm_mma<<<dim3(E / BN, T / BM), 256, smem>>>(tokH, tokL, wtH, wtL, f3, bv, T, E, E);

    // q^T, k^T (split+transpose), v (split)
    splitT_kernel<<<dim3(E / 32, T / 32), blkT>>>(f1, qtH, qtL, T, E);
    splitT_kernel<<<dim3(E / 32, T / 32), blkT>>>(f2, ktH, ktL, T, E);
    split_kernel<<<(unsigned)(TE4 / 256), 256>>>(f3, vH, vL, TE4);

    // logits S[E,E] = q^T k  (A=qt [E,T], B=kt [E,T], K=T)
    gemm_mma<<<dim3(E / BN, E / BM), 256, smem>>>(qtH, qtL, ktH, ktL, S, nullptr, E, E, T);

    // softmax rows (in place)
    softmax_rows<<<E, 256>>>(S, E);

    // att split
    split_kernel<<<(unsigned)(EE4 / 256), 256>>>(S, attH, attL, EE4);

    // out[E,T] = att @ v^T  (A=att [E,E], B=v [T,E], K=E) -> f1
    gemm_mma<<<dim3(T / BN, E / BM), 256, smem>>>(attH, attL, vH, vL, f1, nullptr, E, T, E);

    // out split (reuse tok buffers)
    split_kernel<<<(unsigned)(TE4 / 256), 256>>>(f1, tokH, tokL, TE4);

    // result[E,T] = out @ Wp^T-layout + bp  (A=out [E,T], B=Wp^T [T,T], K=T)
    gemm_mma<<<dim3(T / BN, E / BM), 256, smem>>>(tokH, tokL, wpH, wpL, out, bp, E, T, T);
}